// round 7
// baseline (speedup 1.0000x reference)
#include <cuda_runtime.h>
#include <cstdint>

// Moment feature expansion, order 4, latent dim 16.
// out[b,t,:] = [1, x(16), f2(136), f3(816), f4(3876)] -> 4845 channels.
// Round 7: pairwise scheme with ONE flag per pair (ksel == !xsel identity),
// selection done as 2 FMUL + 1 SEL (fma pipe instead of alu), x-offset in
// the top byte (bare SHR extract), f4 table consumed 2 groups (uint4) per
// iteration, __launch_bounds__(256,6) for register headroom.

#define D    16
#define N2   136
#define N3   816
#define N4   3876
#define NOUT 4845
#define NTHREADS 256

#define F2S 137      // floats per f2 copy; copy1 base 548 B == 4 (mod 8)
#define F3S 817      // floats per f3 copy; copy1 base 3268 B == 4 (mod 8)
#define XS  17       // floats per x  copy; copy1 base 68 B == 4 (mod 8)
#define MAXG2 1940   // padded u32 words per f4 phase (16B multiple)

struct Tab2 { uint16_t v[N2]; };
struct Tab4 { uint16_t v[N4]; };
struct Tp3  { uint32_t v[2][408]; };
struct Grp4 { uint32_t v[4][MAXG2]; };

constexpr Tab2 gen2() {
    Tab2 t{}; int m = 0;
    for (int k = 0; k < D; k++)
        for (int j = 0; j <= k; j++)
            t.v[m++] = (uint16_t)((k << 4) | j);
    return t;
}

constexpr Tab4 gen4() {
    Tab4 t{}; int m = 0;
    int off[D] = {};
    for (int j = 0; j < D; j++) {
        int a = D + 2 - j;                       // 18 - j
        off[j] = N3 - a * (a - 1) * (a - 2) / 6;
    }
    for (int k = 0; k < N3; k++)
        for (int j = 0; j < D; j++)
            if (k >= off[j]) t.v[m++] = (uint16_t)((k << 4) | j);
    return t;
}

// Order-3 pair word: [10:0]=f2 byte off (incl parity copy), [11]=reset flag,
// [31:24]=x byte off (incl parity copy).
constexpr Tp3 genP3() {
    Tp3 t{};
    int off[D] = {};
    for (int j = 0; j < D; j++)
        off[j] = N2 - (D - j) * (D - j + 1) / 2;
    uint16_t kk[N3] = {}, jj[N3] = {};
    int m = 0;
    for (int k = 0; k < N2; k++)
        for (int j = 0; j < D; j++)
            if (k >= off[j]) { kk[m] = (uint16_t)k; jj[m] = (uint16_t)j; m++; }
    for (int h = 0; h < 2; h++) {
        int np = (N3 - h) / 2;                   // 408 or 407
        for (int p = 0; p < np; p++) {
            int a = h + 2 * p, b = a + 1;
            uint32_t k2 = kk[a], j = jj[a];
            uint32_t o2 = (k2 & 1u) * (F2S * 4u) + 4u * k2;
            uint32_t ox = (j & 1u) * (XS * 4u) + 4u * j;
            uint32_t fl = (kk[b] != k2) ? 1u : 0u;   // reset <=> !(j+1)
            t.v[h][p] = o2 | (fl << 11) | (ox << 24);
        }
    }
    return t;
}

// Order-4 pair word: [12:0]=f3 byte off (incl parity copy), [13]=reset flag,
// [31:24]=x byte off (incl parity copy).
constexpr Grp4 genG() {
    Grp4 t{};
    int off[D] = {};
    for (int j = 0; j < D; j++) {
        int a = D + 2 - j;
        off[j] = N3 - a * (a - 1) * (a - 2) / 6;
    }
    uint16_t kk[N4] = {}, jj[N4] = {};
    int m = 0;
    for (int k = 0; k < N3; k++)
        for (int j = 0; j < D; j++)
            if (k >= off[j]) { kk[m] = (uint16_t)k; jj[m] = (uint16_t)j; m++; }
    for (int h = 0; h < 4; h++) {
        int nv = (N4 - h) >> 2;
        for (int g = 0; g < nv; g++)
            for (int pr = 0; pr < 2; pr++) {
                int a = h + 4 * g + 2 * pr, b = a + 1;
                uint32_t ka = kk[a], ja = jj[a];
                uint32_t o3 = (ka & 1u) * (F3S * 4u) + 4u * ka;   // 8B aligned
                uint32_t ox = (ja & 1u) * (XS * 4u) + 4u * ja;    // 8B aligned
                uint32_t fl = (kk[b] != ka) ? 1u : 0u;
                t.v[h][2 * g + pr] = o3 | (fl << 13) | (ox << 24);
            }
    }
    return t;
}

__device__ constexpr Tab2 c_t2 = gen2();
__device__ constexpr Tab4 c_t4 = gen4();
__device__ __align__(8)  constexpr Tp3  c_p3 = genP3();
__device__ __align__(16) constexpr Grp4 c_g4 = genG();

// One f4 pair: e0 = f3[k]*x[j]; e1 = reset ? f3[k+1]*x0 : f3[k]*x[j+1].
__device__ __forceinline__ float2 pair4(uint32_t u,
                                        const char* __restrict__ f3b,
                                        const char* __restrict__ xb,
                                        float x0) {
    const float2 f  = *(const float2*)(f3b + (u & 0x1FFFu));
    const float2 xv = *(const float2*)(xb + (u >> 24));
    const float e0   = f.x * xv.x;
    const float cont = f.x * xv.y;
    const float rst  = f.y * x0;
    return make_float2(e0, (u & (1u << 13)) ? rst : cont);
}

__global__ __launch_bounds__(NTHREADS, 6)
void Moment_2774548873409_kernel(const float* __restrict__ in,
                                 float* __restrict__ out,
                                 int rows) {
    __shared__ __align__(16) float f3r[2 * F3S];
    __shared__ __align__(16) float f2r[2 * F2S];
    __shared__ __align__(16) float xr[2 * XS];

    const int row = blockIdx.x;
    if (row >= rows) return;
    const int t = threadIdx.x;

    const size_t gbase = (size_t)row * NOUT;
    float* __restrict__ o = out + gbase;
    const float* __restrict__ xin = in + (size_t)row * D;

    // --- orders 0, 1 (+ pad init) ---
    if (t < D) {
        const float v = xin[t];
        xr[t] = v; xr[XS + t] = v;
        o[1 + t] = v;
    }
    if (t == 0) {
        o[0] = 1.0f;
        xr[D] = 0.0f;  xr[XS + D] = 0.0f;
        f2r[N2] = 0.0f; f2r[F2S + N2] = 0.0f;
        f3r[N3] = 0.0f; f3r[F3S + N3] = 0.0f;
    }
    __syncthreads();
    const float x0 = xr[0];

    // --- order 2 ---
    if (t < N2) {
        const uint16_t p = c_t2.v[t];
        const float v = xr[p >> 4] * xr[p & 15];
        f2r[t] = v; f2r[F2S + t] = v;
        o[17 + t] = v;
    }
    __syncthreads();

    const char* __restrict__ f2b = (const char*)f2r;
    const char* __restrict__ xb  = (const char*)xr;

    // --- order 3: pairwise, direct float2 store (8B-aligned both parities) --
    const int h3 = (int)((gbase + 153) & 1);
    if (h3 == 0) {
        #pragma unroll 2
        for (int p = t; p < 408; p += NTHREADS) {
            const uint32_t w = c_p3.v[0][p];
            const float2 f  = *(const float2*)(f2b + (w & 0x7FFu));
            const float2 xv = *(const float2*)(xb + (w >> 24));
            const float e0 = f.x * xv.x;
            const float e1 = (w & (1u << 11)) ? f.y * x0 : f.x * xv.y;
            const int m = 2 * p;
            *(float2*)(f3r + m) = make_float2(e0, e1);
            f3r[F3S + m] = e0; f3r[F3S + m + 1] = e1;
            *(float2*)(o + 153 + m) = make_float2(e0, e1);
        }
    } else {
        #pragma unroll 2
        for (int p = t; p < 407; p += NTHREADS) {
            const uint32_t w = c_p3.v[1][p];
            const float2 f  = *(const float2*)(f2b + (w & 0x7FFu));
            const float2 xv = *(const float2*)(xb + (w >> 24));
            const float e0 = f.x * xv.x;
            const float e1 = (w & (1u << 11)) ? f.y * x0 : f.x * xv.y;
            const int m = 1 + 2 * p;
            f3r[m] = e0; f3r[m + 1] = e1;
            *(float2*)(f3r + F3S + m) = make_float2(e0, e1);
            *(float2*)(o + 153 + m) = make_float2(e0, e1);
        }
        if (t == 0) {
            const float v = f2r[0] * x0;
            f3r[0] = v; f3r[F3S] = v; o[153] = v;
        }
        if (t == 1) {
            const float v = f2r[135] * xr[15];
            f3r[815] = v; f3r[F3S + 815] = v; o[153 + 815] = v;
        }
    }
    __syncthreads();

    // --- order 4: 2 float4 groups / iteration, uint4 table load -------------
    const char* __restrict__ f3b = (const char*)f3r;
    float* __restrict__ o4 = o + 969;
    const int a4 = (int)((gbase + 969) & 3);
    const int h  = (4 - a4) & 3;

    if (t < h) {
        const uint16_t p = c_t4.v[t];
        o4[t] = f3r[p >> 4] * xr[p & 15];
    }

    const int nv  = (N4 - h) >> 2;
    const int nv2 = nv >> 1;
    const uint4* __restrict__ gt4 = (const uint4*)&c_g4.v[h][0];
    float4* __restrict__ ov = (float4*)(o4 + h);
    #pragma unroll 2
    for (int q = t; q < nv2; q += NTHREADS) {
        const uint4 w = gt4[q];
        const float2 r0 = pair4(w.x, f3b, xb, x0);
        const float2 r1 = pair4(w.y, f3b, xb, x0);
        const float2 r2 = pair4(w.z, f3b, xb, x0);
        const float2 r3 = pair4(w.w, f3b, xb, x0);
        ov[2 * q]     = make_float4(r0.x, r0.y, r1.x, r1.y);
        ov[2 * q + 1] = make_float4(r2.x, r2.y, r3.x, r3.y);
    }

    // Remaining (odd trailing group + end scalars): at most 4 elements.
    const int covered = h + 8 * nv2;
    if (t < N4 - covered) {
        const int m = covered + t;
        const uint16_t p = c_t4.v[m];
        o4[m] = f3r[p >> 4] * xr[p & 15];
    }
}

extern "C" void kernel_launch(void* const* d_in, const int* in_sizes, int n_in,
                              void* d_out, int out_size) {
    const float* in = (const float*)d_in[0];
    float* out = (float*)d_out;
    const int rows = in_sizes[0] / D;            // 8192
    Moment_2774548873409_kernel<<<rows, NTHREADS>>>(in, out, rows);
}

// round 8
// speedup vs baseline: 1.3090x; 1.3090x over previous
#include <cuda_runtime.h>
#include <cstdint>

// Moment feature expansion, order 4, latent dim 16.
// out[b,t,:] = [1, x(16), f2(136), f3(816), f4(3876)] -> 4845 channels.
// Round 8: R6 skeleton (direct stores, pairwise order-3/order-4, uint2 table
// loads, full occupancy) + R7's occupancy-neutral encoding: ONE flag per
// pair (ksel == !xsel), select as 2 FMUL + 1 SEL on the fma pipe, x byte
// offset in the top byte (bare SHR extract). No min-blocks launch bound.

#define D    16
#define N2   136
#define N3   816
#define N4   3876
#define NOUT 4845
#define NTHREADS 256

#define F2S 137      // floats per f2 copy; copy1 base 548 B == 4 (mod 8)
#define F3S 817      // floats per f3 copy; copy1 base 3268 B == 4 (mod 8)
#define XS  17       // floats per x  copy; copy1 base 68 B == 4 (mod 8)
#define MAXG 969     // max float4 groups in f4 (phase 0)

struct Tab2 { uint16_t v[N2]; };
struct Tab4 { uint16_t v[N4]; };
struct Tp3  { uint32_t v[2][408]; };        // [row-parity phase][pair]
struct Grp4 { uint32_t v[4][MAXG * 2]; };   // [gmem phase][group*2 + pair]

constexpr Tab2 gen2() {
    Tab2 t{}; int m = 0;
    for (int k = 0; k < D; k++)
        for (int j = 0; j <= k; j++)
            t.v[m++] = (uint16_t)((k << 4) | j);
    return t;
}

constexpr Tab4 gen4() {
    Tab4 t{}; int m = 0;
    int off[D] = {};
    for (int j = 0; j < D; j++) {
        int a = D + 2 - j;                       // 18 - j
        off[j] = N3 - a * (a - 1) * (a - 2) / 6;
    }
    for (int k = 0; k < N3; k++)
        for (int j = 0; j < D; j++)
            if (k >= off[j]) t.v[m++] = (uint16_t)((k << 4) | j);
    return t;
}

// Order-3 pair word: [10:0]=f2 byte off (incl parity copy), [11]=reset flag,
// [31:24]=x byte off (incl parity copy).
constexpr Tp3 genP3() {
    Tp3 t{};
    int off[D] = {};
    for (int j = 0; j < D; j++)
        off[j] = N2 - (D - j) * (D - j + 1) / 2;
    uint16_t kk[N3] = {}, jj[N3] = {};
    int m = 0;
    for (int k = 0; k < N2; k++)
        for (int j = 0; j < D; j++)
            if (k >= off[j]) { kk[m] = (uint16_t)k; jj[m] = (uint16_t)j; m++; }
    for (int h = 0; h < 2; h++) {
        int np = (N3 - h) / 2;                   // 408 or 407
        for (int p = 0; p < np; p++) {
            int a = h + 2 * p, b = a + 1;
            uint32_t k2 = kk[a], j = jj[a];
            uint32_t o2 = (k2 & 1u) * (F2S * 4u) + 4u * k2;
            uint32_t ox = (j & 1u) * (XS * 4u) + 4u * j;
            uint32_t fl = (kk[b] != k2) ? 1u : 0u;   // reset <=> !(j->j+1)
            t.v[h][p] = o2 | (fl << 11) | (ox << 24);
        }
    }
    return t;
}

// Order-4 pair word: [12:0]=f3 byte off (incl parity copy), [13]=reset flag,
// [31:24]=x byte off (incl parity copy).
constexpr Grp4 genG() {
    Grp4 t{};
    int off[D] = {};
    for (int j = 0; j < D; j++) {
        int a = D + 2 - j;
        off[j] = N3 - a * (a - 1) * (a - 2) / 6;
    }
    uint16_t kk[N4] = {}, jj[N4] = {};
    int m = 0;
    for (int k = 0; k < N3; k++)
        for (int j = 0; j < D; j++)
            if (k >= off[j]) { kk[m] = (uint16_t)k; jj[m] = (uint16_t)j; m++; }
    for (int h = 0; h < 4; h++) {
        int nv = (N4 - h) >> 2;
        for (int g = 0; g < nv; g++)
            for (int pr = 0; pr < 2; pr++) {
                int a = h + 4 * g + 2 * pr, b = a + 1;
                uint32_t ka = kk[a], ja = jj[a];
                uint32_t o3 = (ka & 1u) * (F3S * 4u) + 4u * ka;   // 8B aligned
                uint32_t ox = (ja & 1u) * (XS * 4u) + 4u * ja;    // 8B aligned
                uint32_t fl = (kk[b] != ka) ? 1u : 0u;
                t.v[h][2 * g + pr] = o3 | (fl << 13) | (ox << 24);
            }
    }
    return t;
}

__device__ constexpr Tab2 c_t2 = gen2();
__device__ constexpr Tab4 c_t4 = gen4();
__device__ __align__(8)  constexpr Tp3  c_p3 = genP3();
__device__ __align__(16) constexpr Grp4 c_g4 = genG();

__global__ __launch_bounds__(NTHREADS)
void Moment_2774548873409_kernel(const float* __restrict__ in,
                                 float* __restrict__ out,
                                 int rows) {
    __shared__ __align__(16) float f3r[2 * F3S];   // f3, 2 parity copies
    __shared__ __align__(16) float f2r[2 * F2S];   // f2, 2 parity copies
    __shared__ __align__(16) float xr[2 * XS];     // x,  2 parity copies

    const int row = blockIdx.x;
    if (row >= rows) return;
    const int t = threadIdx.x;

    const size_t gbase = (size_t)row * NOUT;
    float* __restrict__ o = out + gbase;
    const float* __restrict__ xin = in + (size_t)row * D;

    // --- orders 0, 1 (+ pad init) ---
    if (t < D) {
        const float v = xin[t];
        xr[t] = v; xr[XS + t] = v;
        o[1 + t] = v;
    }
    if (t == 0) {
        o[0] = 1.0f;
        xr[D] = 0.0f;   xr[XS + D] = 0.0f;
        f2r[N2] = 0.0f; f2r[F2S + N2] = 0.0f;
        f3r[N3] = 0.0f; f3r[F3S + N3] = 0.0f;
    }
    __syncthreads();
    const float x0 = xr[0];

    // --- order 2: f2[m] = x[k] * x[j], direct store ---
    if (t < N2) {
        const uint16_t p = c_t2.v[t];
        const float v = xr[p >> 4] * xr[p & 15];
        f2r[t] = v; f2r[F2S + t] = v;
        o[17 + t] = v;
    }
    __syncthreads();

    const char* __restrict__ f2b = (const char*)f2r;
    const char* __restrict__ xb  = (const char*)xr;

    // --- order 3: pairwise, direct float2 store (8B-aligned both parities) --
    const int h3 = (int)((gbase + 153) & 1);
    if (h3 == 0) {
        #pragma unroll 2
        for (int p = t; p < 408; p += NTHREADS) {
            const uint32_t w = c_p3.v[0][p];
            const float2 f  = *(const float2*)(f2b + (w & 0x7FFu));
            const float2 xv = *(const float2*)(xb + (w >> 24));
            const float e0 = f.x * xv.x;
            const float e1 = (w & (1u << 11)) ? f.y * x0 : f.x * xv.y;
            const int m = 2 * p;
            *(float2*)(f3r + m) = make_float2(e0, e1);       // copy0 aligned
            f3r[F3S + m] = e0; f3r[F3S + m + 1] = e1;        // copy1 scalar
            *(float2*)(o + 153 + m) = make_float2(e0, e1);
        }
    } else {
        #pragma unroll 2
        for (int p = t; p < 407; p += NTHREADS) {
            const uint32_t w = c_p3.v[1][p];
            const float2 f  = *(const float2*)(f2b + (w & 0x7FFu));
            const float2 xv = *(const float2*)(xb + (w >> 24));
            const float e0 = f.x * xv.x;
            const float e1 = (w & (1u << 11)) ? f.y * x0 : f.x * xv.y;
            const int m = 1 + 2 * p;
            f3r[m] = e0; f3r[m + 1] = e1;                    // copy0 scalar
            *(float2*)(f3r + F3S + m) = make_float2(e0, e1); // copy1 aligned
            *(float2*)(o + 153 + m) = make_float2(e0, e1);
        }
        if (t == 0) {            // f3[0] = f2[0] * x0
            const float v = f2r[0] * x0;
            f3r[0] = v; f3r[F3S] = v; o[153] = v;
        }
        if (t == 1) {            // f3[815] = f2[135] * x[15]
            const float v = f2r[135] * xr[15];
            f3r[815] = v; f3r[F3S + 815] = v; o[153 + 815] = v;
        }
    }
    __syncthreads();

    // --- order 4: pairwise LDS.64, uint2 table load, aligned STG.128 --------
    const char* __restrict__ f3b = (const char*)f3r;
    float* __restrict__ o4 = o + 969;
    const int a4 = (int)((gbase + 969) & 3);
    const int h  = (4 - a4) & 3;

    if (t < h) {
        const uint16_t p = c_t4.v[t];
        o4[t] = f3r[p >> 4] * xr[p & 15];
    }

    const int nv = (N4 - h) >> 2;
    const uint2* __restrict__ gt = (const uint2*)&c_g4.v[h][0];
    float4* __restrict__ ov = (float4*)(o4 + h);
    #pragma unroll 4
    for (int g = t; g < nv; g += NTHREADS) {
        const uint2 w = gt[g];
        float4 r;
        {
            const uint32_t u = w.x;
            const float2 f  = *(const float2*)(f3b + (u & 0x1FFFu));
            const float2 xv = *(const float2*)(xb + (u >> 24));
            r.x = f.x * xv.x;
            r.y = (u & (1u << 13)) ? f.y * x0 : f.x * xv.y;
        }
        {
            const uint32_t u = w.y;
            const float2 f  = *(const float2*)(f3b + (u & 0x1FFFu));
            const float2 xv = *(const float2*)(xb + (u >> 24));
            r.z = f.x * xv.x;
            r.w = (u & (1u << 13)) ? f.y * x0 : f.x * xv.y;
        }
        ov[g] = r;
    }

    const int done = h + 4 * nv;
    if (t < N4 - done) {
        const int m = done + t;
        const uint16_t p = c_t4.v[m];
        o4[m] = f3r[p >> 4] * xr[p & 15];
    }
}

extern "C" void kernel_launch(void* const* d_in, const int* in_sizes, int n_in,
                              void* d_out, int out_size) {
    const float* in = (const float*)d_in[0];
    float* out = (float*)d_out;
    const int rows = in_sizes[0] / D;            // 8192
    Moment_2774548873409_kernel<<<rows, NTHREADS>>>(in, out, rows);
}

// round 10
// speedup vs baseline: 1.3949x; 1.0656x over previous
#include <cuda_runtime.h>
#include <cstdint>

// Moment feature expansion, order 4, latent dim 16.
// out[b,t,:] = [1, x(16), f2(136), f3(816), f4(3876)] -> 4845 channels.
// Round 10: R9 (two phase-matched rows r and r+half per block; table words
// loaded/decoded once, applied to both rows) with the order-2 coverage bug
// fixed: 272 work items now covered by a strided loop (256 threads).

#define D    16
#define N2   136
#define N3   816
#define N4   3876
#define NOUT 4845
#define NTHREADS 256

#define F2S 137      // floats per f2 copy; copy1 base 548 B == 4 (mod 8)
#define F3S 817      // floats per f3 copy; copy1 base 3268 B == 4 (mod 8)
#define XS  17       // floats per x  copy; copy1 base 68 B == 4 (mod 8)
#define MAXG 969     // max float4 groups in f4 (phase 0)

struct Tab2 { uint16_t v[N2]; };
struct Tab4 { uint16_t v[N4]; };
struct Tp3  { uint32_t v[2][408]; };        // [row-parity phase][pair]
struct Grp4 { uint32_t v[4][MAXG * 2]; };   // [gmem phase][group*2 + pair]

constexpr Tab2 gen2() {
    Tab2 t{}; int m = 0;
    for (int k = 0; k < D; k++)
        for (int j = 0; j <= k; j++)
            t.v[m++] = (uint16_t)((k << 4) | j);
    return t;
}

constexpr Tab4 gen4() {
    Tab4 t{}; int m = 0;
    int off[D] = {};
    for (int j = 0; j < D; j++) {
        int a = D + 2 - j;                       // 18 - j
        off[j] = N3 - a * (a - 1) * (a - 2) / 6;
    }
    for (int k = 0; k < N3; k++)
        for (int j = 0; j < D; j++)
            if (k >= off[j]) t.v[m++] = (uint16_t)((k << 4) | j);
    return t;
}

// Order-3 pair word: [10:0]=f2 byte off (incl parity copy), [11]=reset flag,
// [31:24]=x byte off (incl parity copy).
constexpr Tp3 genP3() {
    Tp3 t{};
    int off[D] = {};
    for (int j = 0; j < D; j++)
        off[j] = N2 - (D - j) * (D - j + 1) / 2;
    uint16_t kk[N3] = {}, jj[N3] = {};
    int m = 0;
    for (int k = 0; k < N2; k++)
        for (int j = 0; j < D; j++)
            if (k >= off[j]) { kk[m] = (uint16_t)k; jj[m] = (uint16_t)j; m++; }
    for (int h = 0; h < 2; h++) {
        int np = (N3 - h) / 2;                   // 408 or 407
        for (int p = 0; p < np; p++) {
            int a = h + 2 * p, b = a + 1;
            uint32_t k2 = kk[a], j = jj[a];
            uint32_t o2 = (k2 & 1u) * (F2S * 4u) + 4u * k2;
            uint32_t ox = (j & 1u) * (XS * 4u) + 4u * j;
            uint32_t fl = (kk[b] != k2) ? 1u : 0u;   // reset <=> !(j->j+1)
            t.v[h][p] = o2 | (fl << 11) | (ox << 24);
        }
    }
    return t;
}

// Order-4 pair word: [12:0]=f3 byte off (incl parity copy), [13]=reset flag,
// [31:24]=x byte off (incl parity copy).
constexpr Grp4 genG() {
    Grp4 t{};
    int off[D] = {};
    for (int j = 0; j < D; j++) {
        int a = D + 2 - j;
        off[j] = N3 - a * (a - 1) * (a - 2) / 6;
    }
    uint16_t kk[N4] = {}, jj[N4] = {};
    int m = 0;
    for (int k = 0; k < N3; k++)
        for (int j = 0; j < D; j++)
            if (k >= off[j]) { kk[m] = (uint16_t)k; jj[m] = (uint16_t)j; m++; }
    for (int h = 0; h < 4; h++) {
        int nv = (N4 - h) >> 2;
        for (int g = 0; g < nv; g++)
            for (int pr = 0; pr < 2; pr++) {
                int a = h + 4 * g + 2 * pr, b = a + 1;
                uint32_t ka = kk[a], ja = jj[a];
                uint32_t o3 = (ka & 1u) * (F3S * 4u) + 4u * ka;   // 8B aligned
                uint32_t ox = (ja & 1u) * (XS * 4u) + 4u * ja;    // 8B aligned
                uint32_t fl = (kk[b] != ka) ? 1u : 0u;
                t.v[h][2 * g + pr] = o3 | (fl << 13) | (ox << 24);
            }
    }
    return t;
}

__device__ constexpr Tab2 c_t2 = gen2();
__device__ constexpr Tab4 c_t4 = gen4();
__device__ __align__(8)  constexpr Tp3  c_p3 = genP3();
__device__ __align__(16) constexpr Grp4 c_g4 = genG();

__global__ __launch_bounds__(NTHREADS)
void Moment_2774548873409_kernel(const float* __restrict__ in,
                                 float* __restrict__ out,
                                 int half) {
    __shared__ __align__(16) float f3r[2][2 * F3S];
    __shared__ __align__(16) float f2r[2][2 * F2S];
    __shared__ __align__(16) float xr[2][2 * XS];

    const int t = threadIdx.x;
    const int rowA = blockIdx.x;
    const int rowB = rowA + half;       // half % 4 == 0 -> same phases

    const size_t gA = (size_t)rowA * NOUT;
    const size_t gB = (size_t)rowB * NOUT;
    float* __restrict__ oA = out + gA;
    float* __restrict__ oB = out + gB;

    // --- orders 0, 1 (+ pad init), both rows ---
    if (t < D) {
        const float vA = in[(size_t)rowA * D + t];
        xr[0][t] = vA; xr[0][XS + t] = vA; oA[1 + t] = vA;
        const float vB = in[(size_t)rowB * D + t];
        xr[1][t] = vB; xr[1][XS + t] = vB; oB[1 + t] = vB;
    }
    if (t == 0) {
        oA[0] = 1.0f; oB[0] = 1.0f;
        #pragma unroll
        for (int r = 0; r < 2; r++) {
            xr[r][D] = 0.0f;   xr[r][XS + D] = 0.0f;
            f2r[r][N2] = 0.0f; f2r[r][F2S + N2] = 0.0f;
            f3r[r][N3] = 0.0f; f3r[r][F3S + N3] = 0.0f;
        }
    }
    __syncthreads();
    const float x0A = xr[0][0];
    const float x0B = xr[1][0];

    // --- order 2, both rows: 272 work items, strided (BUGFIX vs R9) ---
    #pragma unroll
    for (int it = t; it < 2 * N2; it += NTHREADS) {
        const int r = (it >= N2) ? 1 : 0;
        const int i = it - r * N2;
        const uint16_t p = c_t2.v[i];
        const float v = xr[r][p >> 4] * xr[r][p & 15];
        f2r[r][i] = v; f2r[r][F2S + i] = v;
        (r ? oB : oA)[17 + i] = v;
    }
    __syncthreads();

    const char* __restrict__ f2bA = (const char*)&f2r[0][0];
    const char* __restrict__ f2bB = (const char*)&f2r[1][0];
    const char* __restrict__ xbA  = (const char*)&xr[0][0];
    const char* __restrict__ xbB  = (const char*)&xr[1][0];

    // --- order 3: decode once, apply to both rows ---
    const int h3 = (int)((gA + 153) & 1);
    if (h3 == 0) {
        #pragma unroll 2
        for (int p = t; p < 408; p += NTHREADS) {
            const uint32_t w  = c_p3.v[0][p];
            const uint32_t o2 = w & 0x7FFu;
            const uint32_t ox = w >> 24;
            const uint32_t fl = w & (1u << 11);
            const int m = 2 * p;
            {
                const float2 f  = *(const float2*)(f2bA + o2);
                const float2 xv = *(const float2*)(xbA + ox);
                const float e0 = f.x * xv.x;
                const float e1 = fl ? f.y * x0A : f.x * xv.y;
                *(float2*)(&f3r[0][m]) = make_float2(e0, e1);
                f3r[0][F3S + m] = e0; f3r[0][F3S + m + 1] = e1;
                *(float2*)(oA + 153 + m) = make_float2(e0, e1);
            }
            {
                const float2 f  = *(const float2*)(f2bB + o2);
                const float2 xv = *(const float2*)(xbB + ox);
                const float e0 = f.x * xv.x;
                const float e1 = fl ? f.y * x0B : f.x * xv.y;
                *(float2*)(&f3r[1][m]) = make_float2(e0, e1);
                f3r[1][F3S + m] = e0; f3r[1][F3S + m + 1] = e1;
                *(float2*)(oB + 153 + m) = make_float2(e0, e1);
            }
        }
    } else {
        #pragma unroll 2
        for (int p = t; p < 407; p += NTHREADS) {
            const uint32_t w  = c_p3.v[1][p];
            const uint32_t o2 = w & 0x7FFu;
            const uint32_t ox = w >> 24;
            const uint32_t fl = w & (1u << 11);
            const int m = 1 + 2 * p;
            {
                const float2 f  = *(const float2*)(f2bA + o2);
                const float2 xv = *(const float2*)(xbA + ox);
                const float e0 = f.x * xv.x;
                const float e1 = fl ? f.y * x0A : f.x * xv.y;
                f3r[0][m] = e0; f3r[0][m + 1] = e1;
                *(float2*)(&f3r[0][F3S + m]) = make_float2(e0, e1);
                *(float2*)(oA + 153 + m) = make_float2(e0, e1);
            }
            {
                const float2 f  = *(const float2*)(f2bB + o2);
                const float2 xv = *(const float2*)(xbB + ox);
                const float e0 = f.x * xv.x;
                const float e1 = fl ? f.y * x0B : f.x * xv.y;
                f3r[1][m] = e0; f3r[1][m + 1] = e1;
                *(float2*)(&f3r[1][F3S + m]) = make_float2(e0, e1);
                *(float2*)(oB + 153 + m) = make_float2(e0, e1);
            }
        }
        if (t == 0) {            // f3[0] = f2[0] * x0
            float v = f2r[0][0] * x0A;
            f3r[0][0] = v; f3r[0][F3S] = v; oA[153] = v;
            v = f2r[1][0] * x0B;
            f3r[1][0] = v; f3r[1][F3S] = v; oB[153] = v;
        }
        if (t == 1) {            // f3[815] = f2[135] * x[15]
            float v = f2r[0][135] * xr[0][15];
            f3r[0][815] = v; f3r[0][F3S + 815] = v; oA[153 + 815] = v;
            v = f2r[1][135] * xr[1][15];
            f3r[1][815] = v; f3r[1][F3S + 815] = v; oB[153 + 815] = v;
        }
    }
    __syncthreads();

    // --- order 4: one table word -> two rows ---
    const char* __restrict__ f3bA = (const char*)&f3r[0][0];
    const char* __restrict__ f3bB = (const char*)&f3r[1][0];
    float* __restrict__ o4A = oA + 969;
    float* __restrict__ o4B = oB + 969;
    const int a4 = (int)((gA + 969) & 3);
    const int h  = (4 - a4) & 3;

    if (t < h) {
        const uint16_t p = c_t4.v[t];
        o4A[t] = f3r[0][p >> 4] * xr[0][p & 15];
        o4B[t] = f3r[1][p >> 4] * xr[1][p & 15];
    }

    const int nv = (N4 - h) >> 2;
    const uint2* __restrict__ gt = (const uint2*)&c_g4.v[h][0];
    float4* __restrict__ ovA = (float4*)(o4A + h);
    float4* __restrict__ ovB = (float4*)(o4B + h);
    #pragma unroll 2
    for (int g = t; g < nv; g += NTHREADS) {
        const uint2 w = gt[g];
        const uint32_t a0 = w.x & 0x1FFFu, b0 = w.x >> 24;
        const uint32_t a1 = w.y & 0x1FFFu, b1 = w.y >> 24;
        const uint32_t f0 = w.x & (1u << 13), f1 = w.y & (1u << 13);
        {
            float4 r;
            const float2 fa = *(const float2*)(f3bA + a0);
            const float2 xa = *(const float2*)(xbA + b0);
            r.x = fa.x * xa.x;
            r.y = f0 ? fa.y * x0A : fa.x * xa.y;
            const float2 fb = *(const float2*)(f3bA + a1);
            const float2 xb2 = *(const float2*)(xbA + b1);
            r.z = fb.x * xb2.x;
            r.w = f1 ? fb.y * x0A : fb.x * xb2.y;
            ovA[g] = r;
        }
        {
            float4 r;
            const float2 fa = *(const float2*)(f3bB + a0);
            const float2 xa = *(const float2*)(xbB + b0);
            r.x = fa.x * xa.x;
            r.y = f0 ? fa.y * x0B : fa.x * xa.y;
            const float2 fb = *(const float2*)(f3bB + a1);
            const float2 xb2 = *(const float2*)(xbB + b1);
            r.z = fb.x * xb2.x;
            r.w = f1 ? fb.y * x0B : fb.x * xb2.y;
            ovB[g] = r;
        }
    }

    const int done = h + 4 * nv;
    if (t < N4 - done) {
        const int m = done + t;
        const uint16_t p = c_t4.v[m];
        o4A[m] = f3r[0][p >> 4] * xr[0][p & 15];
        o4B[m] = f3r[1][p >> 4] * xr[1][p & 15];
    }
}

extern "C" void kernel_launch(void* const* d_in, const int* in_sizes, int n_in,
                              void* d_out, int out_size) {
    const float* in = (const float*)d_in[0];
    float* out = (float*)d_out;
    const int rows = in_sizes[0] / D;            // 8192
    const int half = rows >> 1;                  // 4096, % 4 == 0
    Moment_2774548873409_kernel<<<half, NTHREADS>>>(in, out, half);
}